// round 1
// baseline (speedup 1.0000x reference)
#include <cuda_runtime.h>
#include <math.h>

#define BB 2
#define SS 2048
#define DM 2048
#define NH 16
#define HD 128
#define MR (BB*SS)   // 4096 rows

// ---------------- scratch (static device globals; no allocation) ----------------
__device__ float g_comp[MR*512];
__device__ float g_qr[MR*1024];
__device__ float g_kr[MR*1024];
__device__ float g_qn[MR*1024];
__device__ float g_kn[MR*1024];
__device__ float g_vf[MR*2048];
__device__ float g_Q[(size_t)BB*NH*SS*HD];
__device__ float g_K[(size_t)BB*NH*SS*HD];
__device__ float g_V[(size_t)BB*NH*SS*HD];
__device__ float g_ctx[(size_t)MR*2048];

// ---------------- generic SGEMM: C[M,N] = A[M,K] @ B[K,N] ----------------
// 128x128 tile, BK=16, 256 threads, 8x8 per thread, float4 smem traffic.
__global__ __launch_bounds__(256) void sgemm128(
    const float* __restrict__ A, const float* __restrict__ Bm, float* __restrict__ C,
    int M, int N, int K, int lda, int ldb, int ldc)
{
    __shared__ float As[16][128];
    __shared__ float Bs[16][128];
    const int tid = threadIdx.x;
    const int tx = tid & 15, ty = tid >> 4;
    const int row0 = blockIdx.y << 7, col0 = blockIdx.x << 7;

    float acc[8][8];
#pragma unroll
    for (int i = 0; i < 8; i++)
#pragma unroll
        for (int j = 0; j < 8; j++) acc[i][j] = 0.0f;

    for (int k0 = 0; k0 < K; k0 += 16) {
        // A tile 128x16 (transposed into As[k][m])
#pragma unroll
        for (int it = 0; it < 2; it++) {
            int idx = tid + it * 256;
            int r = idx >> 2, k4 = (idx & 3) << 2;
            float4 a = *(const float4*)(A + (size_t)(row0 + r) * lda + k0 + k4);
            As[k4 + 0][r] = a.x; As[k4 + 1][r] = a.y;
            As[k4 + 2][r] = a.z; As[k4 + 3][r] = a.w;
        }
        // B tile 16x128
#pragma unroll
        for (int it = 0; it < 2; it++) {
            int idx = tid + it * 256;
            int r = idx >> 5, n4 = (idx & 31) << 2;
            *(float4*)(&Bs[r][n4]) = *(const float4*)(Bm + (size_t)(k0 + r) * ldb + col0 + n4);
        }
        __syncthreads();

#pragma unroll
        for (int kk = 0; kk < 16; kk++) {
            float4 a0 = *(const float4*)(&As[kk][ty * 8]);
            float4 a1 = *(const float4*)(&As[kk][ty * 8 + 4]);
            float4 b0 = *(const float4*)(&Bs[kk][tx * 8]);
            float4 b1 = *(const float4*)(&Bs[kk][tx * 8 + 4]);
            float a[8] = {a0.x, a0.y, a0.z, a0.w, a1.x, a1.y, a1.z, a1.w};
            float b[8] = {b0.x, b0.y, b0.z, b0.w, b1.x, b1.y, b1.z, b1.w};
#pragma unroll
            for (int i = 0; i < 8; i++)
#pragma unroll
                for (int j = 0; j < 8; j++) acc[i][j] = fmaf(a[i], b[j], acc[i][j]);
        }
        __syncthreads();
    }

#pragma unroll
    for (int i = 0; i < 8; i++) {
        size_t r = (size_t)(row0 + ty * 8 + i);
        float* dst = C + r * ldc + col0 + tx * 8;
        *(float4*)dst       = make_float4(acc[i][0], acc[i][1], acc[i][2], acc[i][3]);
        *(float4*)(dst + 4) = make_float4(acc[i][4], acc[i][5], acc[i][6], acc[i][7]);
    }
}

// ---------------- build Q/K/V: concat quirk + RoPE + scale-fold ----------------
// q_cat row = [qn(1024) | qr(1024)]; head h takes dims [128h,128h+128).
// First 64 dims pass through; last 64 get RoPE(dim=64, half=32) at position s.
__global__ __launch_bounds__(256) void build_qkv(
    const float* __restrict__ qn, const float* __restrict__ qr,
    const float* __restrict__ kn, const float* __restrict__ kr,
    const float* __restrict__ vf,
    float* __restrict__ Q, float* __restrict__ K, float* __restrict__ V)
{
    const int t = blockIdx.x;           // token 0..4095
    const int b = t / SS, s = t % SS;
    const float qscale = 0.08838834764831845f; // 1/sqrt(128)

    for (int idx = threadIdx.x; idx < NH * HD; idx += blockDim.x) {
        int h = idx / HD, d = idx % HD;
        size_t o = (((size_t)(b * NH + h)) * SS + s) * HD + d;

        V[o] = vf[(size_t)t * 2048 + h * 128 + d];

        float qv, kv;
        if (d < 64) {
            int c = h * 128 + d;
            if (c < 1024) { qv = qn[(size_t)t * 1024 + c];        kv = kn[(size_t)t * 1024 + c]; }
            else          { qv = qr[(size_t)t * 1024 + c - 1024]; kv = kr[(size_t)t * 1024 + c - 1024]; }
        } else {
            int j  = d - 64;
            int jj = (j < 32) ? j : j - 32;
            int c1 = h * 128 + 64 + jj;        // r[jj]
            int c2 = c1 + 32;                  // r[jj+32]
            float r1q, r2q, r1k, r2k;
            if (c1 < 1024) {
                r1q = qn[(size_t)t * 1024 + c1]; r2q = qn[(size_t)t * 1024 + c2];
                r1k = kn[(size_t)t * 1024 + c1]; r2k = kn[(size_t)t * 1024 + c2];
            } else {
                r1q = qr[(size_t)t * 1024 + c1 - 1024]; r2q = qr[(size_t)t * 1024 + c2 - 1024];
                r1k = kr[(size_t)t * 1024 + c1 - 1024]; r2k = kr[(size_t)t * 1024 + c2 - 1024];
            }
            float invf = 1.0f / powf(10000.0f, (float)(2 * jj) / 64.0f);
            float ang = (float)s * invf;
            float cs = cosf(ang), sn = sinf(ang);
            if (j < 32) { qv = r1q * cs - r2q * sn; kv = r1k * cs - r2k * sn; }
            else        { qv = r1q * sn + r2q * cs; kv = r1k * sn + r2k * cs; }
        }
        Q[o] = qv * qscale;
        K[o] = kv;
    }
}

// ---------------- flash attention (non-causal), fp32 ----------------
// BM=BN=64, D=128. 256 threads as 16x16; thread owns 4 score rows x 4 cols,
// and 4 O rows x 8 cols. Online softmax with width-16 shuffle reductions.
#define QS_LD 132
#define PS_LD 68
#define SMEM_FLOATS (3*64*QS_LD + 64*PS_LD)
#define SMEM_BYTES (SMEM_FLOATS * 4)

__global__ __launch_bounds__(256) void flash_attn(
    const float* __restrict__ Qg, const float* __restrict__ Kg,
    const float* __restrict__ Vg, float* __restrict__ ctx)
{
    extern __shared__ float sm[];
    float* Qs = sm;
    float* Ks = sm + 64 * QS_LD;
    float* Vs = sm + 2 * 64 * QS_LD;
    float* Ps = sm + 3 * 64 * QS_LD;

    const int tid = threadIdx.x;
    const int tx = tid & 15, ty = tid >> 4;
    const int bh = blockIdx.y;
    const int q0 = blockIdx.x << 6;
    const size_t base = (size_t)bh * SS * HD;

#pragma unroll
    for (int i = 0; i < 8; i++) {
        int idx = tid + i * 256;
        int r = idx >> 5, d4 = (idx & 31) << 2;
        *(float4*)(Qs + r * QS_LD + d4) = *(const float4*)(Qg + base + (size_t)(q0 + r) * HD + d4);
    }

    float m_i[4], l_i[4], acc[4][8];
#pragma unroll
    for (int i = 0; i < 4; i++) {
        m_i[i] = -1e30f; l_i[i] = 0.0f;
#pragma unroll
        for (int c = 0; c < 8; c++) acc[i][c] = 0.0f;
    }

    for (int k0 = 0; k0 < SS; k0 += 64) {
        __syncthreads();  // previous PV done before overwriting K/V
#pragma unroll
        for (int i = 0; i < 8; i++) {
            int idx = tid + i * 256;
            int r = idx >> 5, d4 = (idx & 31) << 2;
            *(float4*)(Ks + r * QS_LD + d4) = *(const float4*)(Kg + base + (size_t)(k0 + r) * HD + d4);
            *(float4*)(Vs + r * QS_LD + d4) = *(const float4*)(Vg + base + (size_t)(k0 + r) * HD + d4);
        }
        __syncthreads();

        float sc[4][4];
#pragma unroll
        for (int i = 0; i < 4; i++)
#pragma unroll
            for (int j = 0; j < 4; j++) sc[i][j] = 0.0f;

#pragma unroll 8
        for (int d4 = 0; d4 < 128; d4 += 4) {
            float4 qv[4], kv[4];
#pragma unroll
            for (int i = 0; i < 4; i++) qv[i] = *(const float4*)(Qs + (4 * ty + i) * QS_LD + d4);
#pragma unroll
            for (int j = 0; j < 4; j++) kv[j] = *(const float4*)(Ks + (4 * tx + j) * QS_LD + d4);
#pragma unroll
            for (int i = 0; i < 4; i++)
#pragma unroll
                for (int j = 0; j < 4; j++)
                    sc[i][j] += qv[i].x * kv[j].x + qv[i].y * kv[j].y +
                                qv[i].z * kv[j].z + qv[i].w * kv[j].w;
        }

        // online softmax per row (rows 4ty..4ty+3; reduce across the 16 tx lanes)
#pragma unroll
        for (int i = 0; i < 4; i++) {
            float mx = fmaxf(fmaxf(sc[i][0], sc[i][1]), fmaxf(sc[i][2], sc[i][3]));
#pragma unroll
            for (int off = 8; off > 0; off >>= 1)
                mx = fmaxf(mx, __shfl_xor_sync(0xffffffffu, mx, off, 16));
            float mnew = fmaxf(m_i[i], mx);
            float corr = expf(m_i[i] - mnew);
            float p0 = expf(sc[i][0] - mnew), p1 = expf(sc[i][1] - mnew);
            float p2 = expf(sc[i][2] - mnew), p3 = expf(sc[i][3] - mnew);
            float rs = p0 + p1 + p2 + p3;
#pragma unroll
            for (int off = 8; off > 0; off >>= 1)
                rs += __shfl_xor_sync(0xffffffffu, rs, off, 16);
            l_i[i] = l_i[i] * corr + rs;
            m_i[i] = mnew;
#pragma unroll
            for (int c = 0; c < 8; c++) acc[i][c] *= corr;
            *(float4*)(Ps + (4 * ty + i) * PS_LD + 4 * tx) = make_float4(p0, p1, p2, p3);
        }
        __syncthreads();

        // O += P @ V
#pragma unroll 4
        for (int j = 0; j < 64; j++) {
            float4 v0 = *(const float4*)(Vs + j * QS_LD + 8 * tx);
            float4 v1 = *(const float4*)(Vs + j * QS_LD + 8 * tx + 4);
#pragma unroll
            for (int i = 0; i < 4; i++) {
                float p = Ps[(4 * ty + i) * PS_LD + j];
                acc[i][0] = fmaf(p, v0.x, acc[i][0]); acc[i][1] = fmaf(p, v0.y, acc[i][1]);
                acc[i][2] = fmaf(p, v0.z, acc[i][2]); acc[i][3] = fmaf(p, v0.w, acc[i][3]);
                acc[i][4] = fmaf(p, v1.x, acc[i][4]); acc[i][5] = fmaf(p, v1.y, acc[i][5]);
                acc[i][6] = fmaf(p, v1.z, acc[i][6]); acc[i][7] = fmaf(p, v1.w, acc[i][7]);
            }
        }
    }

    const int b = bh >> 4, h = bh & 15;
#pragma unroll
    for (int i = 0; i < 4; i++) {
        float inv = 1.0f / l_i[i];
        size_t t = (size_t)b * SS + q0 + 4 * ty + i;
        float* dst = ctx + t * 2048 + h * 128 + 8 * tx;
        *(float4*)dst       = make_float4(acc[i][0] * inv, acc[i][1] * inv, acc[i][2] * inv, acc[i][3] * inv);
        *(float4*)(dst + 4) = make_float4(acc[i][4] * inv, acc[i][5] * inv, acc[i][6] * inv, acc[i][7] * inv);
    }
}

// ---------------- launch ----------------
extern "C" void kernel_launch(void* const* d_in, const int* in_sizes, int n_in,
                              void* d_out, int out_size)
{
    const float* x        = (const float*)d_in[0];
    const float* W_comp   = (const float*)d_in[1];
    const float* W_q_dec  = (const float*)d_in[2];
    const float* W_k_dec  = (const float*)d_in[3];
    const float* W_v_dec  = (const float*)d_in[4];
    const float* W_rope_q = (const float*)d_in[5];
    const float* W_rope_k = (const float*)d_in[6];
    const float* W_out    = (const float*)d_in[7];
    float* out = (float*)d_out;

    float *comp, *qr, *kr, *qn, *kn, *vf, *Q, *K, *V, *ctx;
    cudaGetSymbolAddress((void**)&comp, g_comp);
    cudaGetSymbolAddress((void**)&qr,   g_qr);
    cudaGetSymbolAddress((void**)&kr,   g_kr);
    cudaGetSymbolAddress((void**)&qn,   g_qn);
    cudaGetSymbolAddress((void**)&kn,   g_kn);
    cudaGetSymbolAddress((void**)&vf,   g_vf);
    cudaGetSymbolAddress((void**)&Q,    g_Q);
    cudaGetSymbolAddress((void**)&K,    g_K);
    cudaGetSymbolAddress((void**)&V,    g_V);
    cudaGetSymbolAddress((void**)&ctx,  g_ctx);

    cudaFuncSetAttribute(flash_attn, cudaFuncAttributeMaxDynamicSharedMemorySize, SMEM_BYTES);

    dim3 thr(256);
    // compressed = x @ W_comp            [4096,2048]@[2048,512]
    sgemm128<<<dim3(4, 32), thr>>>(x, W_comp, comp, MR, 512, 2048, 2048, 512, 512);
    // q_rope = x @ W_rope_q              [4096,2048]@[2048,1024]
    sgemm128<<<dim3(8, 32), thr>>>(x, W_rope_q, qr, MR, 1024, 2048, 2048, 1024, 1024);
    // k_rope = x @ W_rope_k
    sgemm128<<<dim3(8, 32), thr>>>(x, W_rope_k, kr, MR, 1024, 2048, 2048, 1024, 1024);
    // q_no_rope = c_qk @ W_q_dec         [4096,256(strided 512)]@[256,1024]
    sgemm128<<<dim3(8, 32), thr>>>(comp, W_q_dec, qn, MR, 1024, 256, 512, 1024, 1024);
    // k_no_rope = c_qk @ W_k_dec
    sgemm128<<<dim3(8, 32), thr>>>(comp, W_k_dec, kn, MR, 1024, 256, 512, 1024, 1024);
    // v = c_v @ W_v_dec                  offset +256 into each compressed row
    sgemm128<<<dim3(16, 32), thr>>>(comp + 256, W_v_dec, vf, MR, 2048, 256, 512, 2048, 2048);
    // assemble Q/K/V with RoPE quirk
    build_qkv<<<MR, 256>>>(qn, qr, kn, kr, vf, Q, K, V);
    // attention -> ctx [4096, 2048]
    flash_attn<<<dim3(SS / 64, BB * NH), 256, SMEM_BYTES>>>(Q, K, V, ctx);
    // out = ctx @ W_out                  [4096,2048]@[2048,2048]
    sgemm128<<<dim3(16, 32), thr>>>(ctx, W_out, out, MR, 2048, 2048, 2048, 2048, 2048);
}

// round 2
// speedup vs baseline: 3.3716x; 3.3716x over previous
#include <cuda_runtime.h>
#include <cuda_bf16.h>
#include <math.h>
#include <stdint.h>

#define BB 2
#define SS 2048
#define NH 16
#define HD 128
#define MR (BB*SS)   // 4096 rows

// ---------------- scratch (static device globals; no allocation) ----------------
__device__ float g_comp[MR*512];
__device__ float g_qr[MR*1024];
__device__ float g_kr[MR*1024];
__device__ float g_qn[MR*1024];
__device__ float g_kn[MR*1024];
__device__ float g_vf[MR*2048];
__device__ float g_Q[(size_t)BB*NH*SS*HD];
__device__ float g_K[(size_t)BB*NH*SS*HD];
__device__ float g_V[(size_t)BB*NH*SS*HD];
__device__ float g_ctx[(size_t)MR*2048];

// ---------------- bf16-split helpers ----------------
// pack two consecutive-k floats into (hi bf16x2, lo bf16x2) where lo = x - hi.
__device__ __forceinline__ void split2(float f0, float f1, uint32_t& hi, uint32_t& lo) {
    __nv_bfloat162 h = __floats2bfloat162_rn(f0, f1);
    float r0 = f0 - __bfloat162float(h.x);
    float r1 = f1 - __bfloat162float(h.y);
    __nv_bfloat162 l = __floats2bfloat162_rn(r0, r1);
    hi = *reinterpret_cast<uint32_t*>(&h);
    lo = *reinterpret_cast<uint32_t*>(&l);
}

// m16n8k16 row.col bf16 mma, fp32 accumulate in place.
__device__ __forceinline__ void mma16(float* c, const uint32_t* a, const uint32_t* b) {
    asm volatile(
        "mma.sync.aligned.m16n8k16.row.col.f32.bf16.bf16.f32 "
        "{%0,%1,%2,%3},{%4,%5,%6,%7},{%8,%9},{%0,%1,%2,%3};"
        : "+f"(c[0]), "+f"(c[1]), "+f"(c[2]), "+f"(c[3])
        : "r"(a[0]), "r"(a[1]), "r"(a[2]), "r"(a[3]), "r"(b[0]), "r"(b[1]));
}

// ---------------- GEMM: C[M,N] = A[M,K] @ B[K,N], bf16-split tensor cores ----
// 128x128 block tile, 8 warps (64x32 each), BK=16 (one k16 step), double-buffered.
// smem holds k-pair-packed words: sA[buf][hi/lo][kp][m], sB[buf][hi/lo][kp][n].
#define GLD 136

__global__ __launch_bounds__(256, 1) void gemm_bf16s(
    const float* __restrict__ A, const float* __restrict__ B, float* __restrict__ C,
    int M, int N, int K, int lda, int ldb, int ldc)
{
    __shared__ uint32_t sA[2][2][8 * GLD];
    __shared__ uint32_t sB[2][2][8 * GLD];

    const int tid = threadIdx.x, lane = tid & 31, warp = tid >> 5;
    const int grp = lane >> 2, qid = lane & 3;
    const int wm = (warp & 1) * 64, wn = (warp >> 1) * 32;
    const size_t row0 = (size_t)blockIdx.y * 128, col0 = (size_t)blockIdx.x * 128;

    float acc[4][4][4];
#pragma unroll
    for (int mt = 0; mt < 4; mt++)
#pragma unroll
        for (int nt = 0; nt < 4; nt++)
#pragma unroll
            for (int i = 0; i < 4; i++) acc[mt][nt][i] = 0.0f;

    const int ar  = tid >> 2;          // 0..63 (second row ar+64)
    const int ak4 = (tid & 3) << 2;    // 0,4,8,12
    const int bkp = tid >> 5;          // 0..7 (k-pair row)
    const int bn4 = (tid & 31) << 2;   // 0..124

    const float* Ag  = A + (row0 + ar) * lda + ak4;
    const float* Ag2 = A + (row0 + ar + 64) * lda + ak4;
    const float* Bg  = B + col0 + bn4;

    float4 a0r, a1r, b0r, b1r;
    a0r = *(const float4*)(Ag);
    a1r = *(const float4*)(Ag2);
    b0r = *(const float4*)(Bg + (size_t)(2 * bkp) * ldb);
    b1r = *(const float4*)(Bg + (size_t)(2 * bkp + 1) * ldb);

    int buf = 0;
    {   // store iter 0
        uint32_t h, l;
        int kp0 = ak4 >> 1;
        split2(a0r.x, a0r.y, h, l); sA[buf][0][kp0 * GLD + ar] = h;       sA[buf][1][kp0 * GLD + ar] = l;
        split2(a0r.z, a0r.w, h, l); sA[buf][0][(kp0 + 1) * GLD + ar] = h; sA[buf][1][(kp0 + 1) * GLD + ar] = l;
        split2(a1r.x, a1r.y, h, l); sA[buf][0][kp0 * GLD + ar + 64] = h;       sA[buf][1][kp0 * GLD + ar + 64] = l;
        split2(a1r.z, a1r.w, h, l); sA[buf][0][(kp0 + 1) * GLD + ar + 64] = h; sA[buf][1][(kp0 + 1) * GLD + ar + 64] = l;
        uint32_t hb[4], lb[4];
        split2(b0r.x, b1r.x, hb[0], lb[0]);
        split2(b0r.y, b1r.y, hb[1], lb[1]);
        split2(b0r.z, b1r.z, hb[2], lb[2]);
        split2(b0r.w, b1r.w, hb[3], lb[3]);
        *(uint4*)&sB[buf][0][bkp * GLD + bn4] = make_uint4(hb[0], hb[1], hb[2], hb[3]);
        *(uint4*)&sB[buf][1][bkp * GLD + bn4] = make_uint4(lb[0], lb[1], lb[2], lb[3]);
    }
    __syncthreads();

    const int NI = K >> 4;
    for (int it = 0; it < NI; it++) {
        if (it + 1 < NI) {
            int k0 = (it + 1) << 4;
            a0r = *(const float4*)(Ag + k0);
            a1r = *(const float4*)(Ag2 + k0);
            b0r = *(const float4*)(Bg + (size_t)(k0 + 2 * bkp) * ldb);
            b1r = *(const float4*)(Bg + (size_t)(k0 + 2 * bkp + 1) * ldb);
        }

        // compute this buffer (one k16 step)
        uint32_t ah[4][4], al[4][4], bh[4][2], bl[4][2];
#pragma unroll
        for (int mt = 0; mt < 4; mt++) {
            int m = wm + mt * 16 + grp;
            ah[mt][0] = sA[buf][0][qid * GLD + m];
            ah[mt][1] = sA[buf][0][qid * GLD + m + 8];
            ah[mt][2] = sA[buf][0][(qid + 4) * GLD + m];
            ah[mt][3] = sA[buf][0][(qid + 4) * GLD + m + 8];
            al[mt][0] = sA[buf][1][qid * GLD + m];
            al[mt][1] = sA[buf][1][qid * GLD + m + 8];
            al[mt][2] = sA[buf][1][(qid + 4) * GLD + m];
            al[mt][3] = sA[buf][1][(qid + 4) * GLD + m + 8];
        }
#pragma unroll
        for (int nt = 0; nt < 4; nt++) {
            int n = wn + nt * 8 + grp;
            bh[nt][0] = sB[buf][0][qid * GLD + n];
            bh[nt][1] = sB[buf][0][(qid + 4) * GLD + n];
            bl[nt][0] = sB[buf][1][qid * GLD + n];
            bl[nt][1] = sB[buf][1][(qid + 4) * GLD + n];
        }
#pragma unroll
        for (int mt = 0; mt < 4; mt++)
#pragma unroll
            for (int nt = 0; nt < 4; nt++) {
                mma16(acc[mt][nt], ah[mt], bh[nt]);
                mma16(acc[mt][nt], ah[mt], bl[nt]);
                mma16(acc[mt][nt], al[mt], bh[nt]);
            }

        if (it + 1 < NI) {
            buf ^= 1;
            uint32_t h, l;
            int kp0 = ak4 >> 1;
            split2(a0r.x, a0r.y, h, l); sA[buf][0][kp0 * GLD + ar] = h;       sA[buf][1][kp0 * GLD + ar] = l;
            split2(a0r.z, a0r.w, h, l); sA[buf][0][(kp0 + 1) * GLD + ar] = h; sA[buf][1][(kp0 + 1) * GLD + ar] = l;
            split2(a1r.x, a1r.y, h, l); sA[buf][0][kp0 * GLD + ar + 64] = h;       sA[buf][1][kp0 * GLD + ar + 64] = l;
            split2(a1r.z, a1r.w, h, l); sA[buf][0][(kp0 + 1) * GLD + ar + 64] = h; sA[buf][1][(kp0 + 1) * GLD + ar + 64] = l;
            uint32_t hb[4], lb[4];
            split2(b0r.x, b1r.x, hb[0], lb[0]);
            split2(b0r.y, b1r.y, hb[1], lb[1]);
            split2(b0r.z, b1r.z, hb[2], lb[2]);
            split2(b0r.w, b1r.w, hb[3], lb[3]);
            *(uint4*)&sB[buf][0][bkp * GLD + bn4] = make_uint4(hb[0], hb[1], hb[2], hb[3]);
            *(uint4*)&sB[buf][1][bkp * GLD + bn4] = make_uint4(lb[0], lb[1], lb[2], lb[3]);
            __syncthreads();
        }
    }

    // epilogue: c0,c1 -> (row, 2qid), c2,c3 -> (row+8, 2qid)
#pragma unroll
    for (int mt = 0; mt < 4; mt++) {
        size_t r = row0 + wm + mt * 16 + grp;
#pragma unroll
        for (int nt = 0; nt < 4; nt++) {
            size_t c = col0 + wn + nt * 8 + 2 * qid;
            *(float2*)(C + r * ldc + c)       = make_float2(acc[mt][nt][0], acc[mt][nt][1]);
            *(float2*)(C + (r + 8) * ldc + c) = make_float2(acc[mt][nt][2], acc[mt][nt][3]);
        }
    }
}

// ---------------- build Q/K/V: concat quirk + RoPE + scale-fold ----------------
__global__ __launch_bounds__(256) void build_qkv(
    const float* __restrict__ qn, const float* __restrict__ qr,
    const float* __restrict__ kn, const float* __restrict__ kr,
    const float* __restrict__ vf,
    float* __restrict__ Q, float* __restrict__ K, float* __restrict__ V)
{
    const int t = blockIdx.x;           // token 0..4095
    const int b = t / SS, s = t % SS;
    const float qscale = 0.08838834764831845f; // 1/sqrt(128)

    for (int idx = threadIdx.x; idx < NH * HD; idx += blockDim.x) {
        int h = idx / HD, d = idx % HD;
        size_t o = (((size_t)(b * NH + h)) * SS + s) * HD + d;

        V[o] = vf[(size_t)t * 2048 + h * 128 + d];

        float qv, kv;
        if (d < 64) {
            int c = h * 128 + d;
            if (c < 1024) { qv = qn[(size_t)t * 1024 + c];        kv = kn[(size_t)t * 1024 + c]; }
            else          { qv = qr[(size_t)t * 1024 + c - 1024]; kv = kr[(size_t)t * 1024 + c - 1024]; }
        } else {
            int j  = d - 64;
            int jj = (j < 32) ? j : j - 32;
            int c1 = h * 128 + 64 + jj;
            int c2 = c1 + 32;
            float r1q, r2q, r1k, r2k;
            if (c1 < 1024) {
                r1q = qn[(size_t)t * 1024 + c1]; r2q = qn[(size_t)t * 1024 + c2];
                r1k = kn[(size_t)t * 1024 + c1]; r2k = kn[(size_t)t * 1024 + c2];
            } else {
                r1q = qr[(size_t)t * 1024 + c1 - 1024]; r2q = qr[(size_t)t * 1024 + c2 - 1024];
                r1k = kr[(size_t)t * 1024 + c1 - 1024]; r2k = kr[(size_t)t * 1024 + c2 - 1024];
            }
            float invf = 1.0f / powf(10000.0f, (float)(2 * jj) / 64.0f);
            float ang = (float)s * invf;
            float cs = cosf(ang), sn = sinf(ang);
            if (j < 32) { qv = r1q * cs - r2q * sn; kv = r1k * cs - r2k * sn; }
            else        { qv = r1q * sn + r2q * cs; kv = r1k * sn + r2k * cs; }
        }
        Q[o] = qv * qscale;
        K[o] = kv;
    }
}

// ---------------- flash attention on tensor cores (bf16-split) ----------------
// BM=128 (8 warps x 16 rows), BN=64, D=128. All operands hi/lo split.
#define QLD 68    // 64 packed-d words + pad
#define VLD 136   // 128 d cols + pad
#define PLD 36    // 32 packed-kv words + pad

#define ATT_SMEM_WORDS (2*128*QLD + 2*64*QLD + 2*32*VLD + 2*128*PLD)
#define ATT_SMEM_BYTES (ATT_SMEM_WORDS * 4)

__global__ __launch_bounds__(256, 1) void attn_mma(
    const float* __restrict__ Qg, const float* __restrict__ Kg,
    const float* __restrict__ Vg, float* __restrict__ ctx)
{
    extern __shared__ uint32_t smw[];
    uint32_t* Qh = smw;
    uint32_t* Ql = Qh + 128 * QLD;
    uint32_t* Kh = Ql + 128 * QLD;
    uint32_t* Kl = Kh + 64 * QLD;
    uint32_t* Vh = Kl + 64 * QLD;
    uint32_t* Vl = Vh + 32 * VLD;
    uint32_t* Ph = Vl + 32 * VLD;
    uint32_t* Pl = Ph + 128 * PLD;

    const int tid = threadIdx.x, lane = tid & 31, warp = tid >> 5;
    const int grp = lane >> 2, qid = lane & 3;
    const int bh = blockIdx.y;
    const int q0 = blockIdx.x << 7;
    const size_t base = (size_t)bh * SS * HD;
    const int r0 = warp * 16;

    // load Q tile 128x128 -> packed hi/lo
#pragma unroll
    for (int i = 0; i < 16; i++) {
        int idx = tid + i * 256;
        int r = idx >> 5, c4 = (idx & 31) << 2;
        float4 v = *(const float4*)(Qg + base + (size_t)(q0 + r) * HD + c4);
        uint32_t h0, l0, h1, l1;
        split2(v.x, v.y, h0, l0);
        split2(v.z, v.w, h1, l1);
        int w = r * QLD + (c4 >> 1);
        *(uint2*)&Qh[w] = make_uint2(h0, h1);
        *(uint2*)&Ql[w] = make_uint2(l0, l1);
    }

    float m0 = -1e30f, m1 = -1e30f, l0s = 0.0f, l1s = 0.0f;
    float o[16][4];
#pragma unroll
    for (int t = 0; t < 16; t++)
#pragma unroll
        for (int i = 0; i < 4; i++) o[t][i] = 0.0f;

    for (int kv0 = 0; kv0 < SS; kv0 += 64) {
        __syncthreads();   // prior PV reads of Vh/Vl done
        // K tile 64x128
#pragma unroll
        for (int i = 0; i < 8; i++) {
            int idx = tid + i * 256;
            int r = idx >> 5, c4 = (idx & 31) << 2;
            float4 v = *(const float4*)(Kg + base + (size_t)(kv0 + r) * HD + c4);
            uint32_t h0, l0, h1, l1;
            split2(v.x, v.y, h0, l0);
            split2(v.z, v.w, h1, l1);
            int w = r * QLD + (c4 >> 1);
            *(uint2*)&Kh[w] = make_uint2(h0, h1);
            *(uint2*)&Kl[w] = make_uint2(l0, l1);
        }
        // V tile 64x128, packed along kv pairs
#pragma unroll
        for (int i = 0; i < 4; i++) {
            int kvp = (tid >> 5) + i * 8;      // 0..31
            int c4 = (tid & 31) << 2;
            float4 v0 = *(const float4*)(Vg + base + (size_t)(kv0 + 2 * kvp) * HD + c4);
            float4 v1 = *(const float4*)(Vg + base + (size_t)(kv0 + 2 * kvp + 1) * HD + c4);
            uint32_t hb[4], lb[4];
            split2(v0.x, v1.x, hb[0], lb[0]);
            split2(v0.y, v1.y, hb[1], lb[1]);
            split2(v0.z, v1.z, hb[2], lb[2]);
            split2(v0.w, v1.w, hb[3], lb[3]);
            *(uint4*)&Vh[kvp * VLD + c4] = make_uint4(hb[0], hb[1], hb[2], hb[3]);
            *(uint4*)&Vl[kvp * VLD + c4] = make_uint4(lb[0], lb[1], lb[2], lb[3]);
        }
        __syncthreads();

        // ---- S = Q K^T (rows r0..r0+15 of this warp, all 64 kv) ----
        float s[8][4];
#pragma unroll
        for (int nt = 0; nt < 8; nt++)
#pragma unroll
            for (int i = 0; i < 4; i++) s[nt][i] = 0.0f;

#pragma unroll
        for (int ks = 0; ks < 8; ks++) {
            int kp = ks * 8;
            uint32_t ah[4], al[4];
            ah[0] = Qh[(r0 + grp) * QLD + kp + qid];
            ah[1] = Qh[(r0 + grp + 8) * QLD + kp + qid];
            ah[2] = Qh[(r0 + grp) * QLD + kp + qid + 4];
            ah[3] = Qh[(r0 + grp + 8) * QLD + kp + qid + 4];
            al[0] = Ql[(r0 + grp) * QLD + kp + qid];
            al[1] = Ql[(r0 + grp + 8) * QLD + kp + qid];
            al[2] = Ql[(r0 + grp) * QLD + kp + qid + 4];
            al[3] = Ql[(r0 + grp + 8) * QLD + kp + qid + 4];
#pragma unroll
            for (int nt = 0; nt < 8; nt++) {
                uint32_t b2h[2], b2l[2];
                b2h[0] = Kh[(nt * 8 + grp) * QLD + kp + qid];
                b2h[1] = Kh[(nt * 8 + grp) * QLD + kp + qid + 4];
                b2l[0] = Kl[(nt * 8 + grp) * QLD + kp + qid];
                b2l[1] = Kl[(nt * 8 + grp) * QLD + kp + qid + 4];
                mma16(s[nt], ah, b2h);
                mma16(s[nt], ah, b2l);
                mma16(s[nt], al, b2h);
            }
        }

        // ---- online softmax (rows: a = r0+grp, b = r0+grp+8) ----
        float mxa = -1e30f, mxb = -1e30f;
#pragma unroll
        for (int nt = 0; nt < 8; nt++) {
            mxa = fmaxf(mxa, fmaxf(s[nt][0], s[nt][1]));
            mxb = fmaxf(mxb, fmaxf(s[nt][2], s[nt][3]));
        }
        mxa = fmaxf(mxa, __shfl_xor_sync(0xffffffffu, mxa, 1));
        mxa = fmaxf(mxa, __shfl_xor_sync(0xffffffffu, mxa, 2));
        mxb = fmaxf(mxb, __shfl_xor_sync(0xffffffffu, mxb, 1));
        mxb = fmaxf(mxb, __shfl_xor_sync(0xffffffffu, mxb, 2));
        float mna = fmaxf(m0, mxa), mnb = fmaxf(m1, mxb);
        float ca = __expf(m0 - mna), cb = __expf(m1 - mnb);
        float rsa = 0.0f, rsb = 0.0f;
#pragma unroll
        for (int nt = 0; nt < 8; nt++) {
            s[nt][0] = __expf(s[nt][0] - mna);
            s[nt][1] = __expf(s[nt][1] - mna);
            s[nt][2] = __expf(s[nt][2] - mnb);
            s[nt][3] = __expf(s[nt][3] - mnb);
            rsa += s[nt][0] + s[nt][1];
            rsb += s[nt][2] + s[nt][3];
        }
        rsa += __shfl_xor_sync(0xffffffffu, rsa, 1);
        rsa += __shfl_xor_sync(0xffffffffu, rsa, 2);
        rsb += __shfl_xor_sync(0xffffffffu, rsb, 1);
        rsb += __shfl_xor_sync(0xffffffffu, rsb, 2);
        l0s = l0s * ca + rsa;
        l1s = l1s * cb + rsb;
        m0 = mna; m1 = mnb;
#pragma unroll
        for (int t = 0; t < 16; t++) {
            o[t][0] *= ca; o[t][1] *= ca;
            o[t][2] *= cb; o[t][3] *= cb;
        }

        // ---- stage P (packed kv pairs), own-warp rows only ----
#pragma unroll
        for (int nt = 0; nt < 8; nt++) {
            uint32_t h, l;
            split2(s[nt][0], s[nt][1], h, l);
            Ph[(r0 + grp) * PLD + 4 * nt + qid] = h;
            Pl[(r0 + grp) * PLD + 4 * nt + qid] = l;
            split2(s[nt][2], s[nt][3], h, l);
            Ph[(r0 + grp + 8) * PLD + 4 * nt + qid] = h;
            Pl[(r0 + grp + 8) * PLD + 4 * nt + qid] = l;
        }
        __syncwarp();

        // ---- O += P @ V ----
#pragma unroll
        for (int ks = 0; ks < 4; ks++) {
            int kp = ks * 8;
            uint32_t ah[4], al[4];
            ah[0] = Ph[(r0 + grp) * PLD + kp + qid];
            ah[1] = Ph[(r0 + grp + 8) * PLD + kp + qid];
            ah[2] = Ph[(r0 + grp) * PLD + kp + qid + 4];
            ah[3] = Ph[(r0 + grp + 8) * PLD + kp + qid + 4];
            al[0] = Pl[(r0 + grp) * PLD + kp + qid];
            al[1] = Pl[(r0 + grp + 8) * PLD + kp + qid];
            al[2] = Pl[(r0 + grp) * PLD + kp + qid + 4];
            al[3] = Pl[(r0 + grp + 8) * PLD + kp + qid + 4];
#pragma unroll
            for (int nt = 0; nt < 16; nt++) {
                uint32_t b2h[2], b2l[2];
                b2h[0] = Vh[(kp + qid) * VLD + nt * 8 + grp];
                b2h[1] = Vh[(kp + qid + 4) * VLD + nt * 8 + grp];
                b2l[0] = Vl[(kp + qid) * VLD + nt * 8 + grp];
                b2l[1] = Vl[(kp + qid + 4) * VLD + nt * 8 + grp];
                mma16(o[nt], ah, b2h);
                mma16(o[nt], ah, b2l);
                mma16(o[nt], al, b2h);
            }
        }
    }

    // ---- epilogue: normalize and write ctx [token][2048] ----
    float ia = 1.0f / l0s, ib = 1.0f / l1s;
    const int b = bh >> 4, h = bh & 15;
    const size_t ta = (size_t)b * SS + q0 + r0 + grp;
    const size_t tb = ta + 8;
#pragma unroll
    for (int nt = 0; nt < 16; nt++) {
        size_t c = (size_t)h * 128 + nt * 8 + 2 * qid;
        *(float2*)(ctx + ta * 2048 + c) = make_float2(o[nt][0] * ia, o[nt][1] * ia);
        *(float2*)(ctx + tb * 2048 + c) = make_float2(o[nt][2] * ib, o[nt][3] * ib);
    }
}

// ---------------- launch ----------------
extern "C" void kernel_launch(void* const* d_in, const int* in_sizes, int n_in,
                              void* d_out, int out_size)
{
    const float* x        = (const float*)d_in[0];
    const float* W_comp   = (const float*)d_in[1];
    const float* W_q_dec  = (const float*)d_in[2];
    const float* W_k_dec  = (const float*)d_in[3];
    const float* W_v_dec  = (const float*)d_in[4];
    const float* W_rope_q = (const float*)d_in[5];
    const float* W_rope_k = (const float*)d_in[6];
    const float* W_out    = (const float*)d_in[7];
    float* out = (float*)d_out;

    float *comp, *qr, *kr, *qn, *kn, *vf, *Q, *K, *V, *ctx;
    cudaGetSymbolAddress((void**)&comp, g_comp);
    cudaGetSymbolAddress((void**)&qr,   g_qr);
    cudaGetSymbolAddress((void**)&kr,   g_kr);
    cudaGetSymbolAddress((void**)&qn,   g_qn);
    cudaGetSymbolAddress((void**)&kn,   g_kn);
    cudaGetSymbolAddress((void**)&vf,   g_vf);
    cudaGetSymbolAddress((void**)&Q,    g_Q);
    cudaGetSymbolAddress((void**)&K,    g_K);
    cudaGetSymbolAddress((void**)&V,    g_V);
    cudaGetSymbolAddress((void**)&ctx,  g_ctx);

    cudaFuncSetAttribute(attn_mma, cudaFuncAttributeMaxDynamicSharedMemorySize, ATT_SMEM_BYTES);

    dim3 thr(256);
    // compressed = x @ W_comp            [4096,2048]@[2048,512]
    gemm_bf16s<<<dim3(4, 32), thr>>>(x, W_comp, comp, MR, 512, 2048, 2048, 512, 512);
    // q_rope = x @ W_rope_q              [4096,2048]@[2048,1024]
    gemm_bf16s<<<dim3(8, 32), thr>>>(x, W_rope_q, qr, MR, 1024, 2048, 2048, 1024, 1024);
    // k_rope = x @ W_rope_k
    gemm_bf16s<<<dim3(8, 32), thr>>>(x, W_rope_k, kr, MR, 1024, 2048, 2048, 1024, 1024);
    // q_no_rope = c_qk @ W_q_dec         [4096,256 (lda=512)]@[256,1024]
    gemm_bf16s<<<dim3(8, 32), thr>>>(comp, W_q_dec, qn, MR, 1024, 256, 512, 1024, 1024);
    // k_no_rope = c_qk @ W_k_dec
    gemm_bf16s<<<dim3(8, 32), thr>>>(comp, W_k_dec, kn, MR, 1024, 256, 512, 1024, 1024);
    // v = c_v @ W_v_dec                  offset +256 into each compressed row
    gemm_bf16s<<<dim3(16, 32), thr>>>(comp + 256, W_v_dec, vf, MR, 2048, 256, 512, 2048, 2048);
    // assemble Q/K/V with RoPE quirk (Q pre-scaled by 1/sqrt(128))
    build_qkv<<<MR, 256>>>(qn, qr, kn, kr, vf, Q, K, V);
    // flash attention -> ctx [4096, 2048]
    attn_mma<<<dim3(SS / 128, BB * NH), thr, ATT_SMEM_BYTES>>>(Q, K, V, ctx);
    // out = ctx @ W_out                  [4096,2048]@[2048,2048]
    gemm_bf16s<<<dim3(16, 32), thr>>>(ctx, W_out, out, MR, 2048, 2048, 2048, 2048, 2048);
}